// round 2
// baseline (speedup 1.0000x reference)
#include <cuda_runtime.h>

#define BB 256
#define LL 1024
#define DD 126
#define TT 128
#define NEGV -10000.0f
#define KOFF 8.0f   // constant per-step growth offset for the normalizer

__device__ int g_perm[BB];

// Rank batches by length (descending, index tie-break). O(n^2) rank, n=256.
__global__ void rank_kernel(const int* __restrict__ x_len) {
    __shared__ int lens[BB];
    int t = threadIdx.x;
    lens[t] = x_len[t];
    __syncthreads();
    int mylen = lens[t];
    int r = 0;
    for (int j = 0; j < BB; ++j) {
        int lj = lens[j];
        if (lj > mylen || (lj == mylen && j < t)) r++;
    }
    g_perm[r] = t;
}

__device__ __forceinline__ unsigned long long packf2(float lo, float hi) {
    unsigned long long r;
    asm("mov.b64 %0, {%1, %2};" : "=l"(r) : "f"(lo), "f"(hi));
    return r;
}
__device__ __forceinline__ void unpackf2(unsigned long long v, float& lo, float& hi) {
    asm("mov.b64 {%0, %1}, %2;" : "=f"(lo), "=f"(hi) : "l"(v));
}
__device__ __forceinline__ unsigned long long fma2(unsigned long long a,
                                                   unsigned long long b,
                                                   unsigned long long c) {
    unsigned long long d;
    asm("fma.rn.f32x2 %0, %1, %2, %3;" : "=l"(d) : "l"(a), "l"(b), "l"(c));
    return d;
}

__global__ __launch_bounds__(TT) void crf_kernel(
    const float* __restrict__ x,
    const float* __restrict__ trans,
    const int*   __restrict__ x_len,
    const int*   __restrict__ tags,
    float*       __restrict__ out)
{
    __shared__ float sh_e[2][TT];   // exp(alpha - C), double-buffered
    __shared__ float sh_d[2];       // normalizer offset for step l (slot l&1)
    __shared__ float sh_red[12];    // 4 warps x {v, em, tr}

    int i = threadIdx.x;
    // Length-balanced batch assignment: bid k and k+148 share an SM (classic LUT).
    int b = g_perm[blockIdx.x < 148 ? blockIdx.x : 403 - blockIdx.x];
    int len = x_len[b];

    if (i < 2) sh_d[i] = 0.f;
    sh_e[0][i] = (i == DD) ? 1.f : 0.f;   // alpha0: only START=126 is exp(0)=1

    // exp(transitions) row i -> 64 packed f32x2 registers
    unsigned long long eT2[64];
    const float* trow = trans + i * TT;
#pragma unroll
    for (int k = 0; k < 64; ++k) {
        float a = __expf(trow[2 * k]);
        float c = __expf(trow[2 * k + 1]);
        eT2[k] = packf2(a, c);
    }
    float eTstop = __expf(trans[127 * TT + i]);   // exp(T[STOP, i])

    // Emission + transition score: parallel over l, strided by 128 threads.
    const int*   tgb = tags + b * LL;
    const float* xb  = x + (size_t)b * LL * DD;
    float em = 0.f, tr = 0.f;
    for (int l = i; l < len; l += TT) {
        int tg = tgb[l];
        em += xb[(size_t)l * DD + tg];
        int prev = (l > 0) ? tgb[l - 1] : DD;      // START
        tr += trans[tg * TT + prev];
        if (l == len - 1) tr += trans[127 * TT + tg];  // STOP <- last
    }

    __syncthreads();

    // ---- forward scan ----
    const float* xrow = xb + i;           // x[b, l, i]
    bool isTag = (i < DD);
    float lg0 = isTag ? xrow[0] : NEGV;
    float lg1 = (len > 1 && isTag) ? xrow[DD] : NEGV;
    float C = 0.f;
    float laste = 0.f;
    int buf = 0;

    for (int l = 0; l < len; ++l) {
        // prefetch logit, distance 2
        float lg2 = ((l + 2) < len && isTag) ? xrow[(size_t)(l + 2) * DD] : NEGV;
        float d = sh_d[l & 1];
        const ulonglong2* ep = (const ulonglong2*)(sh_e[buf]);
        unsigned long long a0, a1, a2, a3;
        a0 = a1 = a2 = a3 = 0ULL;
#pragma unroll
        for (int jc = 0; jc < 32; jc += 2) {
            ulonglong2 ev = ep[jc];
            a0 = fma2(eT2[2 * jc],     ev.x, a0);
            a1 = fma2(eT2[2 * jc + 1], ev.y, a1);
            ulonglong2 ev2 = ep[jc + 1];
            a2 = fma2(eT2[2 * jc + 2], ev2.x, a2);
            a3 = fma2(eT2[2 * jc + 3], ev2.y, a3);
        }
        float s0, s1, s2, s3, s4, s5, s6, s7;
        unpackf2(a0, s0, s1); unpackf2(a1, s2, s3);
        unpackf2(a2, s4, s5); unpackf2(a3, s6, s7);
        float s = ((s0 + s1) + (s2 + s3)) + ((s4 + s5) + (s6 + s7));

        float u  = lg0 + __logf(s);
        float bn = u - d;                 // = alpha_{l+1}[i] - alpha_l[0] - KOFF (bounded)
        float e  = __expf(bn);
        sh_e[buf ^ 1][i] = e;
        // Publish NORMALIZED value + constant growth offset: no feedback recurrence.
        if (i == 0) sh_d[(l + 1) & 1] = bn + KOFF;
        C += d;
        laste = e;
        lg0 = lg1; lg1 = lg2;
        buf ^= 1;
        __syncthreads();
    }

    // ---- partition + output ----
    float v = laste * eTstop;     // exp(alpha_i - C) * exp(T[STOP,i])
    float emv = em, trv = tr;
#pragma unroll
    for (int o = 16; o; o >>= 1) {
        v   += __shfl_xor_sync(0xffffffffu, v, o);
        emv += __shfl_xor_sync(0xffffffffu, emv, o);
        trv += __shfl_xor_sync(0xffffffffu, trv, o);
    }
    int w = i >> 5;
    if ((i & 31) == 0) { sh_red[w] = v; sh_red[4 + w] = emv; sh_red[8 + w] = trv; }
    __syncthreads();
    if (i == 0) {
        float S = (sh_red[0] + sh_red[1]) + (sh_red[2] + sh_red[3]);
        float E = (sh_red[4] + sh_red[5]) + (sh_red[6] + sh_red[7]);
        float R = (sh_red[8] + sh_red[9]) + (sh_red[10] + sh_red[11]);
        float partition = C + __logf(S);
        out[b] = R + E - partition;
    }
}

extern "C" void kernel_launch(void* const* d_in, const int* in_sizes, int n_in,
                              void* d_out, int out_size) {
    const float* x     = (const float*)d_in[0];
    const float* trans = (const float*)d_in[1];
    // d_in[2] = x_mask (unused; derived from x_len since mask is a prefix mask)
    const int*   xlen  = (const int*)d_in[3];
    const int*   tags  = (const int*)d_in[4];
    float* out = (float*)d_out;

    rank_kernel<<<1, BB>>>(xlen);
    crf_kernel<<<BB, TT>>>(x, trans, xlen, tags, out);
}

// round 3
// speedup vs baseline: 1.7354x; 1.7354x over previous
#include <cuda_runtime.h>
#include <cuda_bf16.h>

#define BB 256
#define LL 1024
#define DD 126
#define TT 128
#define NEGV -10000.0f
#define KOFF 8.0f   // constant per-step growth offset for the normalizer

__device__ int g_perm[BB];

// Rank batches by length (descending, index tie-break). O(n^2) rank, n=256.
__global__ void rank_kernel(const int* __restrict__ x_len) {
    __shared__ int lens[BB];
    int t = threadIdx.x;
    lens[t] = x_len[t];
    __syncthreads();
    int mylen = lens[t];
    int r = 0;
    for (int j = 0; j < BB; ++j) {
        int lj = lens[j];
        if (lj > mylen || (lj == mylen && j < t)) r++;
    }
    g_perm[r] = t;
}

__device__ __forceinline__ __nv_bfloat162 asbf2(unsigned u) {
    return *reinterpret_cast<__nv_bfloat162*>(&u);
}

__global__ __launch_bounds__(TT) void crf_kernel(
    const float* __restrict__ x,
    const float* __restrict__ trans,
    const int*   __restrict__ x_len,
    const int*   __restrict__ tags,
    float*       __restrict__ out)
{
    __shared__ __nv_bfloat162 sh_e[2][TT / 2];  // exp(alpha - C) as bf16 pairs, double-buffered
    __shared__ float sh_d[2];                   // normalizer offset for step l (slot l&1)
    __shared__ float sh_red[12];                // 4 warps x {v, em, tr}

    int i = threadIdx.x;
    // Length-balanced batch assignment: bid k and k+148 share an SM (classic LUT).
    int b = g_perm[blockIdx.x < 148 ? blockIdx.x : 403 - blockIdx.x];
    int len = x_len[b];

    if (i < 2) sh_d[i] = 0.f;
    if (i < TT / 2) {
        // alpha0: only START=126 is exp(0)=1; pair p holds states (2p, 2p+1)
        float lo = (2 * i == DD) ? 1.f : 0.f;
        float hi = (2 * i + 1 == DD) ? 1.f : 0.f;
        sh_e[0][i] = __floats2bfloat162_rn(lo, hi);
    }

    // exp(transitions) row i -> 64 packed bf16x2 j-pair registers
    __nv_bfloat162 m2[64];
    const float* trow = trans + i * TT;
#pragma unroll
    for (int p = 0; p < 64; ++p) {
        m2[p] = __floats2bfloat162_rn(__expf(trow[2 * p]), __expf(trow[2 * p + 1]));
    }
    float eTstop = __expf(trans[127 * TT + i]);   // exp(T[STOP, i])

    // Emission + transition score: parallel over l, strided by 128 threads.
    const int*   tgb = tags + b * LL;
    const float* xb  = x + (size_t)b * LL * DD;
    float em = 0.f, tr = 0.f;
    for (int l = i; l < len; l += TT) {
        int tg = tgb[l];
        em += xb[(size_t)l * DD + tg];
        int prev = (l > 0) ? tgb[l - 1] : DD;      // START
        tr += trans[tg * TT + prev];
        if (l == len - 1) tr += trans[127 * TT + tg];  // STOP <- last
    }

    __syncthreads();

    // ---- forward scan ----
    const float* xrow = xb + i;           // x[b, l, i]
    bool isTag = (i < DD);
    float lg0 = isTag ? xrow[0] : NEGV;
    float lg1 = (len > 1 && isTag) ? xrow[DD] : NEGV;
    float C = 0.f;
    float laste = 0.f;
    int buf = 0;

    const __nv_bfloat162 zz = __floats2bfloat162_rn(0.f, 0.f);

    for (int l = 0; l < len; ++l) {
        // prefetch logit, distance 2
        float lg2 = ((l + 2) < len && isTag) ? xrow[(size_t)(l + 2) * DD] : NEGV;
        float d = sh_d[l & 1];
        const uint4* ep = (const uint4*)(sh_e[buf]);

        // 8 bf16x2 accumulators -> per-accumulator chains of 8 HFMA2 (bounded bf16 error)
        __nv_bfloat162 a0 = zz, a1 = zz, a2 = zz, a3 = zz, a4 = zz, a5 = zz, a6 = zz, a7 = zz;
#pragma unroll
        for (int q = 0; q < 16; q += 2) {
            uint4 v0 = ep[q];
            uint4 v1 = ep[q + 1];
            a0 = __hfma2(m2[4 * q + 0], asbf2(v0.x), a0);
            a1 = __hfma2(m2[4 * q + 1], asbf2(v0.y), a1);
            a2 = __hfma2(m2[4 * q + 2], asbf2(v0.z), a2);
            a3 = __hfma2(m2[4 * q + 3], asbf2(v0.w), a3);
            a4 = __hfma2(m2[4 * q + 4], asbf2(v1.x), a4);
            a5 = __hfma2(m2[4 * q + 5], asbf2(v1.y), a5);
            a6 = __hfma2(m2[4 * q + 6], asbf2(v1.z), a6);
            a7 = __hfma2(m2[4 * q + 7], asbf2(v1.w), a7);
        }
        // Combine the 8 partial accumulators in fp32 (cheap; we're crossbar-bound)
        float2 f0 = __bfloat1622float2(a0);
        float2 f1 = __bfloat1622float2(a1);
        float2 f2 = __bfloat1622float2(a2);
        float2 f3 = __bfloat1622float2(a3);
        float2 f4 = __bfloat1622float2(a4);
        float2 f5 = __bfloat1622float2(a5);
        float2 f6 = __bfloat1622float2(a6);
        float2 f7 = __bfloat1622float2(a7);
        float s = (((f0.x + f0.y) + (f1.x + f1.y)) + ((f2.x + f2.y) + (f3.x + f3.y)))
                + (((f4.x + f4.y) + (f5.x + f5.y)) + ((f6.x + f6.y) + (f7.x + f7.y)));

        float u  = lg0 + __logf(s);
        float bn = u - d;                 // = alpha_{l+1}[i] - alpha_l[0] - KOFF (bounded)
        float e  = __expf(bn);
        ((__nv_bfloat16*)sh_e[buf ^ 1])[i] = __float2bfloat16(e);
        // Publish NORMALIZED value + constant growth offset: no feedback recurrence.
        if (i == 0) sh_d[(l + 1) & 1] = bn + KOFF;
        C += d;
        laste = e;
        lg0 = lg1; lg1 = lg2;
        buf ^= 1;
        __syncthreads();
    }

    // ---- partition + output ----
    float v = laste * eTstop;     // exp(alpha_i - C) * exp(T[STOP,i])
    float emv = em, trv = tr;
#pragma unroll
    for (int o = 16; o; o >>= 1) {
        v   += __shfl_xor_sync(0xffffffffu, v, o);
        emv += __shfl_xor_sync(0xffffffffu, emv, o);
        trv += __shfl_xor_sync(0xffffffffu, trv, o);
    }
    int w = i >> 5;
    if ((i & 31) == 0) { sh_red[w] = v; sh_red[4 + w] = emv; sh_red[8 + w] = trv; }
    __syncthreads();
    if (i == 0) {
        float S = (sh_red[0] + sh_red[1]) + (sh_red[2] + sh_red[3]);
        float E = (sh_red[4] + sh_red[5]) + (sh_red[6] + sh_red[7]);
        float R = (sh_red[8] + sh_red[9]) + (sh_red[10] + sh_red[11]);
        float partition = C + __logf(S);
        out[b] = R + E - partition;
    }
}

extern "C" void kernel_launch(void* const* d_in, const int* in_sizes, int n_in,
                              void* d_out, int out_size) {
    const float* x     = (const float*)d_in[0];
    const float* trans = (const float*)d_in[1];
    // d_in[2] = x_mask (unused; derived from x_len since mask is a prefix mask)
    const int*   xlen  = (const int*)d_in[3];
    const int*   tags  = (const int*)d_in[4];
    float* out = (float*)d_out;

    rank_kernel<<<1, BB>>>(xlen);
    crf_kernel<<<BB, TT>>>(x, trans, xlen, tags, out);
}